// round 8
// baseline (speedup 1.0000x reference)
#include <cuda_runtime.h>

#define NB 32
#define NCH 3
#define THREADS 128
#define B_PER_CHUNK 32
#define CHUNK_ELEMS (512*512)
#define CHUNK_F4   (CHUNK_ELEMS/4)         // 65536 float4 per (n,c) chunk
#define NCHUNKS    (16*3)                  // 48
#define NBLOCKS    (NCHUNKS * B_PER_CHUNK) // 1536 small blocks -> HW load balance
#define STRIDE     (B_PER_CHUNK * THREADS) // 4096

// Global accumulators. Zero-initialized at module load; final_kernel resets
// them after reading, so every (graph-replayed) launch starts from zero.
__device__ double g_sum_d[NCH * NB];
__device__ double g_cnt [NCH * NB];

__device__ __forceinline__ void accum(float* sd, unsigned short* scn,
                                      float xc, float pc, float tc, int tid)
{
    int b = (int)(xc * 32.0f);        // inputs uniform [0,1)
    b = min(b, NB - 1);               // x slightly <1 can round x*32 up to 32.0
    int a = b * THREADS + tid;
    sd [a] += pc - tc;                // LDS.32/STS.32, conflict-free (stride 4B)
    scn[a] = (unsigned short)(scn[a] + 1);  // u16, 2-way conflict, max 64/thread/bin
}

__global__ __launch_bounds__(THREADS, 9)
void hist_kernel(const float4* __restrict__ pred,
                 const float4* __restrict__ targ,
                 const float4* __restrict__ x)
{
    // Per-thread privatized histograms, split to shrink smem to 24KB:
    //   diff  fp32 [bin*128 + tid]  (16 KB)
    //   count u16  [bin*128 + tid]  ( 8 KB)  -- count <= 64 fits exactly
    __shared__ float          sd [NB * THREADS];
    __shared__ unsigned short scn[NB * THREADS];

    const int tid = threadIdx.x;

    #pragma unroll
    for (int b = 0; b < NB; b++) {
        sd [b * THREADS + tid] = 0.0f;
        scn[b * THREADS + tid] = 0;
    }
    __syncthreads();

    const int chunk = blockIdx.x / B_PER_CHUNK;   // (n*3 + c)
    const int sub   = blockIdx.x % B_PER_CHUNK;
    const int chan  = chunk % NCH;
    const size_t base = (size_t)chunk * CHUNK_F4;

    // 16 float4 slots per thread, processed as 8 iterations of a slot-pair.
    int i = sub * THREADS + tid;
    #pragma unroll 2
    for (int k = 0; k < CHUNK_F4 / (2 * STRIDE); k++, i += 2 * STRIDE) {
        float4 xa = __ldcs(&x   [base + i]);
        float4 pa = __ldcs(&pred[base + i]);
        float4 ta = __ldcs(&targ[base + i]);
        float4 xb = __ldcs(&x   [base + i + STRIDE]);
        float4 pb = __ldcs(&pred[base + i + STRIDE]);
        float4 tb = __ldcs(&targ[base + i + STRIDE]);

        accum(sd, scn, xa.x, pa.x, ta.x, tid);
        accum(sd, scn, xa.y, pa.y, ta.y, tid);
        accum(sd, scn, xa.z, pa.z, ta.z, tid);
        accum(sd, scn, xa.w, pa.w, ta.w, tid);

        accum(sd, scn, xb.x, pb.x, tb.x, tid);
        accum(sd, scn, xb.y, pb.y, tb.y, tid);
        accum(sd, scn, xb.z, pb.z, tb.z, tid);
        accum(sd, scn, xb.w, pb.w, tb.w, tid);
    }
    __syncthreads();

    // Block reduce: 128 threads = 32 bins x 4 quarters of 32 entries.
    const int bin = tid >> 2;
    const int j   = tid & 3;
    const int bi  = bin * THREADS + j * 32;

    float vd = 0.0f, vc = 0.0f;
    #pragma unroll
    for (int k = 0; k < 32; k++) {
        int kk = (k + tid) & 31;
        vd += sd [bi + kk];
        vc += (float)scn[bi + kk];
    }

    vd += __shfl_down_sync(0xffffffffu, vd, 1);
    vc += __shfl_down_sync(0xffffffffu, vc, 1);
    vd += __shfl_down_sync(0xffffffffu, vd, 2);
    vc += __shfl_down_sync(0xffffffffu, vc, 2);

    if (j == 0) {
        int g = chan * NB + bin;
        atomicAdd(&g_sum_d[g], (double)vd);
        atomicAdd(&g_cnt [g], (double)vc);
    }
}

__global__ void final_kernel(float* __restrict__ out) {
    // PDL: launched early; wait until hist_kernel's writes are visible.
    cudaGridDependencySynchronize();

    int i = threadIdx.x;
    float d = 0.0f;
    if (i < NCH * NB) {
        float cnt = (float)g_cnt[i];
        float sdv = (float)g_sum_d[i];
        if (cnt > 0.0f) d = fabsf(sdv / cnt);
        g_sum_d[i] = 0.0;   // reset for next launch (graph determinism)
        g_cnt [i] = 0.0;
    }
    #pragma unroll
    for (int s = 16; s > 0; s >>= 1)
        d += __shfl_down_sync(0xffffffffu, d, s);

    __shared__ float wsum[4];
    if ((i & 31) == 0) wsum[i >> 5] = d;
    __syncthreads();
    if (i == 0) out[0] = (wsum[0] + wsum[1] + wsum[2] + wsum[3]) / 96.0f;
}

extern "C" void kernel_launch(void* const* d_in, const int* in_sizes, int n_in,
                              void* d_out, int out_size)
{
    const float4* pred = (const float4*)d_in[0];
    const float4* targ = (const float4*)d_in[1];
    const float4* x    = (const float4*)d_in[2];
    float* out = (float*)d_out;

    hist_kernel<<<NBLOCKS, THREADS>>>(pred, targ, x);

    // Programmatic dependent launch: overlap final_kernel's launch latency
    // with hist_kernel execution; correctness via cudaGridDependencySynchronize.
    cudaLaunchConfig_t cfg = {};
    cfg.gridDim  = dim3(1, 1, 1);
    cfg.blockDim = dim3(128, 1, 1);
    cfg.dynamicSmemBytes = 0;
    cfg.stream = 0;
    cudaLaunchAttribute attr[1];
    attr[0].id = cudaLaunchAttributeProgrammaticStreamSerialization;
    attr[0].val.programmaticStreamSerializationAllowed = 1;
    cfg.attrs = attr;
    cfg.numAttrs = 1;
    cudaLaunchKernelEx(&cfg, final_kernel, out);
}

// round 9
// speedup vs baseline: 1.0169x; 1.0169x over previous
#include <cuda_runtime.h>

#define NB 32
#define NCH 3
#define THREADS 128
#define B_PER_CHUNK 32
#define CHUNK_ELEMS (512*512)
#define CHUNK_F4   (CHUNK_ELEMS/4)         // 65536 float4 per (n,c) chunk
#define NCHUNKS    (16*3)                  // 48
#define NBLOCKS    (NCHUNKS * B_PER_CHUNK) // 1536 small blocks -> HW load balance
#define STRIDE     (B_PER_CHUNK * THREADS) // 4096

// Global accumulators. Zero-initialized at module load; the LAST block resets
// them after reading, so every (graph-replayed) launch starts from zero.
__device__ double g_sum_d[NCH * NB];
__device__ double g_cnt [NCH * NB];
__device__ unsigned int g_ticket;

__device__ __forceinline__ void accum(float2* h, float xc, float pc, float tc, int tid)
{
    int b = (int)(xc * 32.0f);        // inputs uniform [0,1)
    b = min(b, NB - 1);               // x slightly <1 can round x*32 up to 32.0
    float2* e = &h[b * THREADS + tid];
    float2 v = *e;                    // LDS.64, conflict-free (lane stride 8B)
    v.x += pc - tc;
    v.y += 1.0f;
    *e = v;                           // STS.64
}

__global__ __launch_bounds__(THREADS, 7)
void fused_kernel(const float4* __restrict__ pred,
                  const float4* __restrict__ targ,
                  const float4* __restrict__ x,
                  float* __restrict__ out)
{
    // Per-thread privatized {sum(p-t), count} histogram: h[bin*128 + tid].
    __shared__ float2 h[NB * THREADS];
    __shared__ bool   s_last;

    const int tid = threadIdx.x;

    #pragma unroll
    for (int b = 0; b < NB; b++)
        h[b * THREADS + tid] = make_float2(0.0f, 0.0f);
    __syncthreads();

    const int chunk = blockIdx.x / B_PER_CHUNK;   // (n*3 + c)
    const int sub   = blockIdx.x % B_PER_CHUNK;
    const int chan  = chunk % NCH;
    const size_t base = (size_t)chunk * CHUNK_F4;

    int i = sub * THREADS + tid;
    #pragma unroll 2
    for (int k = 0; k < CHUNK_F4 / (2 * STRIDE); k++, i += 2 * STRIDE) {
        float4 xa = __ldcs(&x   [base + i]);
        float4 pa = __ldcs(&pred[base + i]);
        float4 ta = __ldcs(&targ[base + i]);
        float4 xb = __ldcs(&x   [base + i + STRIDE]);
        float4 pb = __ldcs(&pred[base + i + STRIDE]);
        float4 tb = __ldcs(&targ[base + i + STRIDE]);

        accum(h, xa.x, pa.x, ta.x, tid);
        accum(h, xa.y, pa.y, ta.y, tid);
        accum(h, xa.z, pa.z, ta.z, tid);
        accum(h, xa.w, pa.w, ta.w, tid);

        accum(h, xb.x, pb.x, tb.x, tid);
        accum(h, xb.y, pb.y, tb.y, tid);
        accum(h, xb.z, pb.z, tb.z, tid);
        accum(h, xb.w, pb.w, tb.w, tid);
    }
    __syncthreads();

    // Block reduce: 128 threads = 32 bins x 4 quarters of 32 entries.
    const int bin = tid >> 2;
    const int j   = tid & 3;
    const int bi  = bin * THREADS + j * 32;

    float vd = 0.0f, vc = 0.0f;
    #pragma unroll
    for (int k = 0; k < 32; k++) {
        int kk = (k + tid) & 31;
        float2 e = h[bi + kk];
        vd += e.x;
        vc += e.y;
    }

    vd += __shfl_down_sync(0xffffffffu, vd, 1);
    vc += __shfl_down_sync(0xffffffffu, vc, 1);
    vd += __shfl_down_sync(0xffffffffu, vd, 2);
    vc += __shfl_down_sync(0xffffffffu, vc, 2);

    if (j == 0) {
        int g = chan * NB + bin;
        atomicAdd(&g_sum_d[g], (double)vd);   // L2 atomic (bypasses L1)
        atomicAdd(&g_cnt [g], (double)vc);
    }

    // ---- fence-free last-block finalize ----
    // All cross-block data lives in L2 atomics. Ordering: lanes' atomicAdds
    // happen-before tid0 via __syncthreads (already above); tid0 publishes
    // with an acq_rel RMW on the ticket; the last block's acq_rel RMW
    // (reading NBLOCKS-1) synchronizes-with every prior release. No
    // __threadfence -> no CCTL.IVALL L1 flush in the streaming mainloop.
    if (tid == 0) {
        unsigned int t;
        asm volatile("atom.acq_rel.gpu.add.u32 %0, [%1], %2;"
                     : "=r"(t) : "l"(&g_ticket), "r"(1u) : "memory");
        s_last = (t == NBLOCKS - 1);
    }
    __syncthreads();
    if (!s_last) return;

    float d = 0.0f;
    if (tid < NCH * NB) {
        // atomic reads land at the LTS where all prior atomics completed
        double cnt = atomicAdd(&g_cnt [tid], 0.0);
        double sdv = atomicAdd(&g_sum_d[tid], 0.0);
        if (cnt > 0.0) d = (float)fabs(sdv / cnt);
        g_sum_d[tid] = 0.0;       // reset for next launch (graph determinism)
        g_cnt [tid] = 0.0;
    }
    if (tid == 0) g_ticket = 0u;

    #pragma unroll
    for (int s = 16; s > 0; s >>= 1)
        d += __shfl_down_sync(0xffffffffu, d, s);

    __shared__ float wsum[4];
    if ((tid & 31) == 0) wsum[tid >> 5] = d;
    __syncthreads();
    if (tid == 0) out[0] = (wsum[0] + wsum[1] + wsum[2] + wsum[3]) / 96.0f;
}

extern "C" void kernel_launch(void* const* d_in, const int* in_sizes, int n_in,
                              void* d_out, int out_size)
{
    const float4* pred = (const float4*)d_in[0];
    const float4* targ = (const float4*)d_in[1];
    const float4* x    = (const float4*)d_in[2];
    float* out = (float*)d_out;

    fused_kernel<<<NBLOCKS, THREADS>>>(pred, targ, x, out);
}